// round 5
// baseline (speedup 1.0000x reference)
#include <cuda_runtime.h>
#include <cuda_bf16.h>
#include <mma.h>
#include <cstdint>

using namespace nvcuda;

#define DM 512
#define FD 1024
#define NE 8
#define TOPK 2
#define NTOK 4096
#define NSLOT (NTOK*TOPK)

#define BM 128
#define BN 64
#define BK 64
#define LDS 72            // bf16 elems per smem row (64 + 8 pad = 144B, 16B-aligned rows)
#define ASZ (BM*LDS*2)    // 18432
#define GSZ (BN*LDS*2)    // 9216
#define SSZ_GU (ASZ+2*GSZ)   // gateup stage: 36864
#define SSZ_DN (ASZ+GSZ)     // down stage:   27648
#define SMEM_GU (3*SSZ_GU)   // 110592
#define SMEM_DN (3*SSZ_DN)   // 82944
#define MAXTILE 80

// ---------------- scratch -----------------------------------------------------
__device__ __nv_bfloat16 g_xn[NTOK * DM];
__device__ __nv_bfloat16 g_H[NSLOT * FD];
__device__ __nv_bfloat16 g_Wgb[NE * FD * DM];
__device__ __nv_bfloat16 g_Wub[NE * FD * DM];
__device__ __nv_bfloat16 g_Wdb[NE * DM * FD];
__device__ int   g_topidx[NSLOT];
__device__ float g_topw[NSLOT];
__device__ int   g_cnt[NE];
__device__ int   g_off[NE];
__device__ int   g_top1[NE];
__device__ float g_probsum[NE];
__device__ int   g_perm[NSLOT];
__device__ float g_wcomb[NSLOT];
__device__ int   g_tile_e[MAXTILE];
__device__ int   g_tile_m0[MAXTILE];
__device__ int   g_ntile;

// ---------------- cp.async helpers -------------------------------------------
__device__ __forceinline__ void cp16(uint32_t dst, const void* src) {
    asm volatile("cp.async.cg.shared.global [%0], [%1], 16;\n" :: "r"(dst), "l"(src));
}
__device__ __forceinline__ void cp_commit() {
    asm volatile("cp.async.commit_group;\n");
}

// ---------------- K0: weight fp32 -> bf16 (+ zero counters) -------------------
__global__ __launch_bounds__(256) void k_convert(
    const float* __restrict__ Wg, const float* __restrict__ Wu,
    const float* __restrict__ Wd)
{
    if (blockIdx.x == 0 && blockIdx.y == 0 && threadIdx.x < NE) {
        g_cnt[threadIdx.x] = 0; g_top1[threadIdx.x] = 0; g_probsum[threadIdx.x] = 0.f;
    }
    const float* src; __nv_bfloat16* dst;
    if (blockIdx.y == 0)      { src = Wg; dst = g_Wgb; }
    else if (blockIdx.y == 1) { src = Wu; dst = g_Wub; }
    else                      { src = Wd; dst = g_Wdb; }
    size_t i = ((size_t)blockIdx.x * 256 + threadIdx.x) * 4;
    float4 v = *reinterpret_cast<const float4*>(src + i);
    __nv_bfloat162* d2 = reinterpret_cast<__nv_bfloat162*>(dst + i);
    d2[0] = __floats2bfloat162_rn(v.x, v.y);
    d2[1] = __floats2bfloat162_rn(v.z, v.w);
}

// ---------------- K1: RMSNorm + router + residual init ------------------------
__global__ __launch_bounds__(256) void k_norm_router(
    const float* __restrict__ x, const float* __restrict__ norm_w,
    const float* __restrict__ gate_w, float* __restrict__ out)
{
    int token = blockIdx.x;
    int tid   = threadIdx.x;
    __shared__ float s_xn[DM];
    __shared__ float s_red[8];
    __shared__ float s_logit[NE];
    __shared__ float s_prob[NE];

    const float2 v = reinterpret_cast<const float2*>(x + (size_t)token * DM)[tid];
    float ss = v.x * v.x + v.y * v.y;
    #pragma unroll
    for (int o = 16; o; o >>= 1) ss += __shfl_xor_sync(0xffffffffu, ss, o);
    if ((tid & 31) == 0) s_red[tid >> 5] = ss;
    __syncthreads();
    if (tid == 0) {
        float t = 0.f;
        #pragma unroll
        for (int i = 0; i < 8; i++) t += s_red[i];
        s_red[0] = rsqrtf(t / (float)DM + 1e-6f);
    }
    __syncthreads();
    float rstd = s_red[0];
    float2 nw = reinterpret_cast<const float2*>(norm_w)[tid];
    float a0 = v.x * rstd * nw.x;
    float a1 = v.y * rstd * nw.y;
    s_xn[2 * tid]     = a0;
    s_xn[2 * tid + 1] = a1;
    reinterpret_cast<float2*>(out + (size_t)token * DM)[tid] = v;   // residual
    reinterpret_cast<__nv_bfloat162*>(g_xn + (size_t)token * DM)[tid] =
        __floats2bfloat162_rn(a0, a1);
    __syncthreads();

    int w = tid >> 5, lane = tid & 31;
    {
        const float* gw = gate_w + w * DM;
        float acc = 0.f;
        #pragma unroll
        for (int j = lane; j < DM; j += 32) acc += s_xn[j] * gw[j];
        #pragma unroll
        for (int o = 16; o; o >>= 1) acc += __shfl_xor_sync(0xffffffffu, acc, o);
        if (lane == 0) s_logit[w] = acc;
    }
    __syncthreads();

    if (tid == 0) {
        float mx = -1e30f;
        #pragma unroll
        for (int e = 0; e < NE; e++) mx = fmaxf(mx, s_logit[e]);
        float p[NE]; float se = 0.f;
        #pragma unroll
        for (int e = 0; e < NE; e++) { p[e] = expf(s_logit[e] - mx); se += p[e]; }
        float inv = 1.f / se;
        int i1 = 0; float p1 = -1.f;
        #pragma unroll
        for (int e = 0; e < NE; e++) {
            p[e] *= inv; s_prob[e] = p[e];
            if (p[e] > p1) { p1 = p[e]; i1 = e; }
        }
        int i2 = 0; float p2 = -1.f;
        #pragma unroll
        for (int e = 0; e < NE; e++)
            if (e != i1 && p[e] > p2) { p2 = p[e]; i2 = e; }
        float sw = p1 + p2; if (sw < 1e-9f) sw = 1e-9f;
        g_topidx[token * 2]     = i1;
        g_topidx[token * 2 + 1] = i2;
        g_topw[token * 2]       = p1 / sw;
        g_topw[token * 2 + 1]   = p2 / sw;
        atomicAdd(&g_cnt[i1], 1);
        atomicAdd(&g_cnt[i2], 1);
        atomicAdd(&g_top1[i1], 1);
    }
    __syncthreads();
    if (tid < NE) atomicAdd(&g_probsum[tid], s_prob[tid]);
}

// ---------------- K2: offsets + tile map + warp-aggregated scatter -------------
__global__ __launch_bounds__(1024) void k_off_scatter() {
    __shared__ int s_cur[NE];
    int t = threadIdx.x;
    if (t < NE) s_cur[t] = 0;
    if (t == 0) {
        int a = 0, nt = 0;
        #pragma unroll
        for (int e = 0; e < NE; e++) {
            g_off[e] = a;
            int c = g_cnt[e];
            for (int m0 = 0; m0 < c; m0 += BM) {
                g_tile_e[nt] = e; g_tile_m0[nt] = m0; nt++;
            }
            a += c;
        }
        g_ntile = nt;
    }
    __syncthreads();
    int lane = t & 31;
    for (int tok = t; tok < NTOK; tok += 1024) {
        #pragma unroll
        for (int s = 0; s < TOPK; s++) {
            int e = g_topidx[2 * tok + s];
            unsigned m = __match_any_sync(0xffffffffu, e);
            int leader = __ffs(m) - 1;
            int rank = __popc(m & ((1u << lane) - 1u));
            int base = 0;
            if (lane == leader) base = atomicAdd(&s_cur[e], __popc(m));
            base = __shfl_sync(0xffffffffu, base, leader);
            int slot = g_off[e] + base + rank;
            g_perm[slot]  = tok;
            g_wcomb[slot] = g_topw[2 * tok + s];
        }
    }
}

// ---------------- K3: gate+up GEMM + SwiGLU (3-stage, 1 sync/iter) -------------
__global__ __launch_bounds__(256) void k_gateup()
{
    int ti = blockIdx.y;
    if (ti >= g_ntile) return;
    int e   = g_tile_e[ti];
    int m0  = g_tile_m0[ti];
    int cnt = g_cnt[e];
    int off = g_off[e];
    int f0  = blockIdx.x * BN;

    extern __shared__ char smem[];
    __shared__ int s_row[BM];

    int t = threadIdx.x;
    if (t < BM) { int r = m0 + t; s_row[t] = (r < cnt) ? g_perm[off + r] : 0; }
    __syncthreads();

    const __nv_bfloat16* a_src[4];
    uint32_t a_dst[4];
    uint32_t sbase = (uint32_t)__cvta_generic_to_shared(smem);
    #pragma unroll
    for (int j = 0; j < 4; j++) {
        int u = t * 4 + j;                 // 0..1023 : A = 128 rows x 4 chunks
        int row = u >> 3, q = u & 7;
        a_src[j] = g_xn + (size_t)s_row[row] * DM + q * 8;
        a_dst[j] = sbase + row * (LDS * 2) + q * 16;
    }
    const __nv_bfloat16* g_src[2]; const __nv_bfloat16* u_src[2];
    uint32_t gu_dst[2];
    #pragma unroll
    for (int j = 0; j < 2; j++) {
        int u = t * 2 + j;                 // 0..511 : W = 64 rows x 8 chunks
        int row = u >> 3, q = u & 7;
        g_src[j] = g_Wgb + ((size_t)e * FD + f0 + row) * DM + q * 8;
        u_src[j] = g_Wub + ((size_t)e * FD + f0 + row) * DM + q * 8;
        gu_dst[j] = sbase + row * (LDS * 2) + q * 16;
    }

    auto issue = [&](int k0, int st) {
        uint32_t so = st * SSZ_GU;
        #pragma unroll
        for (int j = 0; j < 4; j++) cp16(a_dst[j] + so, a_src[j] + k0);
        #pragma unroll
        for (int j = 0; j < 2; j++) {
            cp16(gu_dst[j] + so + ASZ,       g_src[j] + k0);
            cp16(gu_dst[j] + so + ASZ + GSZ, u_src[j] + k0);
        }
    };

    int w  = t >> 5;
    int wr = w >> 1;      // 0..3 -> 32-row slice
    int wc = w & 1;       // 0..1 -> 32-col slice

    wmma::fragment<wmma::accumulator, 16, 16, 16, float> accG[2][2], accU[2][2];
    #pragma unroll
    for (int i = 0; i < 2; i++)
        #pragma unroll
        for (int j = 0; j < 2; j++) {
            wmma::fill_fragment(accG[i][j], 0.f);
            wmma::fill_fragment(accU[i][j], 0.f);
        }

    issue(0, 0); cp_commit();
    issue(BK, 1); cp_commit();

    const int nk = DM / BK;   // 8
    for (int c = 0; c < nk; c++) {
        int st = c % 3;
        asm volatile("cp.async.wait_group 1;\n");   // chunk c resident (this thread)
        __syncthreads();                            // global: chunk c ready; iter c-1 compute done
        if (c + 2 < nk) issue((c + 2) * BK, (c + 2) % 3);  // overwrites stage (c-1)%3: safe post-sync
        cp_commit();

        const __nv_bfloat16* pA = (const __nv_bfloat16*)(smem + st * SSZ_GU);
        const __nv_bfloat16* pG = (const __nv_bfloat16*)(smem + st * SSZ_GU + ASZ);
        const __nv_bfloat16* pU = (const __nv_bfloat16*)(smem + st * SSZ_GU + ASZ + GSZ);

        #pragma unroll
        for (int ks = 0; ks < BK / 16; ks++) {
            wmma::fragment<wmma::matrix_a, 16, 16, 16, __nv_bfloat16, wmma::row_major> fa[2];
            wmma::fragment<wmma::matrix_b, 16, 16, 16, __nv_bfloat16, wmma::col_major> fg[2], fu[2];
            #pragma unroll
            for (int i = 0; i < 2; i++)
                wmma::load_matrix_sync(fa[i], pA + (wr * 32 + i * 16) * LDS + ks * 16, LDS);
            #pragma unroll
            for (int j = 0; j < 2; j++) {
                wmma::load_matrix_sync(fg[j], pG + (wc * 32 + j * 16) * LDS + ks * 16, LDS);
                wmma::load_matrix_sync(fu[j], pU + (wc * 32 + j * 16) * LDS + ks * 16, LDS);
            }
            #pragma unroll
            for (int i = 0; i < 2; i++)
                #pragma unroll
                for (int j = 0; j < 2; j++) {
                    wmma::mma_sync(accG[i][j], fa[i], fg[j], accG[i][j]);
                    wmma::mma_sync(accU[i][j], fa[i], fu[j], accU[i][j]);
                }
        }
    }

    // SwiGLU in-register
    #pragma unroll
    for (int i = 0; i < 2; i++)
        #pragma unroll
        for (int j = 0; j < 2; j++)
            #pragma unroll
            for (int k = 0; k < accG[i][j].num_elements; k++) {
                float g = accG[i][j].x[k], uu = accU[i][j].x[k];
                accG[i][j].x[k] = (g / (1.f + __expf(-g))) * uu;
            }

    __syncthreads();   // all warps done reading smem stages
    float* sO = (float*)smem;  // 128 x 68 fp32
    #pragma unroll
    for (int i = 0; i < 2; i++)
        #pragma unroll
        for (int j = 0; j < 2; j++)
            wmma::store_matrix_sync(sO + (wr * 32 + i * 16) * 68 + wc * 32 + j * 16,
                                    accG[i][j], 68, wmma::mem_row_major);
    __syncthreads();

    int lim = cnt - m0; if (lim > BM) lim = BM;
    for (int u = t; u < BM * BN; u += 256) {
        int r = u >> 6, cc = u & 63;
        if (r < lim)
            g_H[(size_t)(off + m0 + r) * FD + f0 + cc] = __float2bfloat16(sO[r * 68 + cc]);
    }
}

// ---------------- K4: down GEMM + weighted scatter-add -------------------------
__global__ __launch_bounds__(256) void k_down(float* __restrict__ out)
{
    int ti = blockIdx.y;
    if (ti >= g_ntile) return;
    int e   = g_tile_e[ti];
    int m0  = g_tile_m0[ti];
    int cnt = g_cnt[e];
    int off = g_off[e];
    int d0  = blockIdx.x * BN;

    extern __shared__ char smem[];
    __shared__ int   s_tok[BM];
    __shared__ float s_w[BM];

    int t = threadIdx.x;
    int lim = cnt - m0; if (lim > BM) lim = BM;
    if (t < BM) {
        if (t < lim) { s_tok[t] = g_perm[off + m0 + t]; s_w[t] = g_wcomb[off + m0 + t]; }
        else         { s_tok[t] = 0; s_w[t] = 0.f; }
    }
    __syncthreads();

    uint32_t sbase = (uint32_t)__cvta_generic_to_shared(smem);
    const __nv_bfloat16* a_src[4];
    uint32_t a_dst[4];
    #pragma unroll
    for (int j = 0; j < 4; j++) {
        int u = t * 4 + j;
        int row = u >> 3, q = u & 7;
        int gr = off + m0 + row; if (gr >= NSLOT) gr = 0;
        a_src[j] = g_H + (size_t)gr * FD + q * 8;
        a_dst[j] = sbase + row * (LDS * 2) + q * 16;
    }
    const __nv_bfloat16* b_src[2];
    uint32_t b_dst[2];
    #pragma unroll
    for (int j = 0; j < 2; j++) {
        int u = t * 2 + j;
        int row = u >> 3, q = u & 7;
        b_src[j] = g_Wdb + ((size_t)e * DM + d0 + row) * FD + q * 8;
        b_dst[j] = sbase + row * (LDS * 2) + q * 16;
    }

    auto issue = [&](int k0, int st) {
        uint32_t so = st * SSZ_DN;
        #pragma unroll
        for (int j = 0; j < 4; j++) cp16(a_dst[j] + so, a_src[j] + k0);
        #pragma unroll
        for (int j = 0; j < 2; j++) cp16(b_dst[j] + so + ASZ, b_src[j] + k0);
    };

    int w  = t >> 5;
    int wr = w >> 1;
    int wc = w & 1;

    wmma::fragment<wmma::accumulator, 16, 16, 16, float> acc[2][2];
    #pragma unroll
    for (int i = 0; i < 2; i++)
        #pragma unroll
        for (int j = 0; j < 2; j++) wmma::fill_fragment(acc[i][j], 0.f);

    issue(0, 0); cp_commit();
    issue(BK, 1); cp_commit();

    const int nk = FD / BK;   // 16
    for (int c = 0; c < nk; c++) {
        int st = c % 3;
        asm volatile("cp.async.wait_group 1;\n");
        __syncthreads();
        if (c + 2 < nk) issue((c + 2) * BK, (c + 2) % 3);
        cp_commit();

        const __nv_bfloat16* pA = (const __nv_bfloat16*)(smem + st * SSZ_DN);
        const __nv_bfloat16* pB = (const __nv_bfloat16*)(smem + st * SSZ_DN + ASZ);

        #pragma unroll
        for (int ks = 0; ks < BK / 16; ks++) {
            wmma::fragment<wmma::matrix_a, 16, 16, 16, __nv_bfloat16, wmma::row_major> fa[2];
            wmma::fragment<wmma::matrix_b, 16, 16, 16, __nv_bfloat16, wmma::col_major> fb[2];
            #pragma unroll
            for (int i = 0; i < 2; i++)
                wmma::load_matrix_sync(fa[i], pA + (wr * 32 + i * 16) * LDS + ks * 16, LDS);
            #pragma unroll
            for (int j = 0; j < 2; j++)
                wmma::load_matrix_sync(fb[j], pB + (wc * 32 + j * 16) * LDS + ks * 16, LDS);
            #pragma unroll
            for (int i = 0; i < 2; i++)
                #pragma unroll
                for (int j = 0; j < 2; j++)
                    wmma::mma_sync(acc[i][j], fa[i], fb[j], acc[i][j]);
        }
    }

    __syncthreads();
    float* sO = (float*)smem;
    #pragma unroll
    for (int i = 0; i < 2; i++)
        #pragma unroll
        for (int j = 0; j < 2; j++)
            wmma::store_matrix_sync(sO + (wr * 32 + i * 16) * 68 + wc * 32 + j * 16,
                                    acc[i][j], 68, wmma::mem_row_major);
    __syncthreads();

    for (int u = t; u < BM * BN; u += 256) {
        int r = u >> 6, cc = u & 63;
        if (r < lim)
            atomicAdd(&out[(size_t)s_tok[r] * DM + d0 + cc], s_w[r] * sO[r * 68 + cc]);
    }
}

// ---------------- K5: aux loss -------------------------------------------------
__global__ void k_aux(float* __restrict__ out, int out_size) {
    if (threadIdx.x == 0) {
        float s = 0.f;
        #pragma unroll
        for (int e = 0; e < NE; e++)
            s += ((float)g_top1[e] / (float)NTOK) * (g_probsum[e] / (float)NTOK);
        s *= (float)NE;
        if (out_size > NTOK * DM) out[NTOK * DM] = s;
    }
}

// ---------------- launch --------------------------------------------------------
extern "C" void kernel_launch(void* const* d_in, const int* in_sizes, int n_in,
                              void* d_out, int out_size)
{
    const float* x      = (const float*)d_in[0];
    const float* norm_w = (const float*)d_in[1];
    const float* gate_w = (const float*)d_in[2];
    const float* Wg     = (const float*)d_in[3];
    const float* Wu     = (const float*)d_in[4];
    const float* Wd     = (const float*)d_in[5];
    float* out = (float*)d_out;

    cudaFuncSetAttribute(k_gateup, cudaFuncAttributeMaxDynamicSharedMemorySize, SMEM_GU);
    cudaFuncSetAttribute(k_down,   cudaFuncAttributeMaxDynamicSharedMemorySize, SMEM_DN);

    k_convert<<<dim3(NE * FD * DM / 4 / 256, 3), 256>>>(Wg, Wu, Wd);
    k_norm_router<<<NTOK, 256>>>(x, norm_w, gate_w, out);
    k_off_scatter<<<1, 1024>>>();
    k_gateup<<<dim3(FD / BN, MAXTILE - 8), 256, SMEM_GU>>>();
    k_down<<<dim3(DM / BN, MAXTILE - 8), 256, SMEM_DN>>>(out);
    k_aux<<<1, 32>>>(out, out_size);
}

// round 8
// speedup vs baseline: 1.4146x; 1.4146x over previous
#include <cuda_runtime.h>
#include <cuda_bf16.h>
#include <cstdint>

#define DM 512
#define FD 1024
#define NE 8
#define TOPK 2
#define NTOK 4096
#define NSLOT (NTOK*TOPK)
#define MAXTILE 72

#define KC 64                   // K elems per chunk (64 bf16 = 128B per row)
#define STAGE_BYTES 32768       // A 16KB + B 16KB
#define NSTAGE 3
#define SMEM_DYN (NSTAGE*STAGE_BYTES)   // 98304

// ---------------- scratch -----------------------------------------------------
__device__ __nv_bfloat16 g_xn[NTOK * DM];
__device__ __nv_bfloat16 g_H[NSLOT * FD];
__device__ __nv_bfloat16 g_Wgb[NE * FD * DM];
__device__ __nv_bfloat16 g_Wub[NE * FD * DM];
__device__ __nv_bfloat16 g_Wdb[NE * DM * FD];
__device__ int   g_topidx[NSLOT];
__device__ float g_topw[NSLOT];
__device__ int   g_cnt[NE];
__device__ int   g_off[NE];
__device__ int   g_top1[NE];
__device__ float g_probsum[NE];
__device__ int   g_perm[NSLOT];
__device__ float g_wcomb[NSLOT];
__device__ int   g_tile_e[MAXTILE];
__device__ int   g_tile_m0[MAXTILE];
__device__ int   g_ntile;

// ---------------- PTX helpers --------------------------------------------------
__device__ __forceinline__ void cp16(uint32_t dst, const void* src) {
    asm volatile("cp.async.cg.shared.global [%0], [%1], 16;\n" :: "r"(dst), "l"(src));
}
__device__ __forceinline__ void cp_commit() {
    asm volatile("cp.async.commit_group;\n");
}
__device__ __forceinline__ uint32_t smem_u32(const void* p) {
    uint32_t a;
    asm("{ .reg .u64 t; cvta.to.shared.u64 t, %1; cvt.u32.u64 %0, t; }" : "=r"(a) : "l"(p));
    return a;
}
__device__ __forceinline__ void ldmx4(uint32_t& r0, uint32_t& r1, uint32_t& r2, uint32_t& r3,
                                      uint32_t addr) {
    asm volatile("ldmatrix.sync.aligned.m8n8.x4.shared.b16 {%0,%1,%2,%3}, [%4];"
        : "=r"(r0), "=r"(r1), "=r"(r2), "=r"(r3) : "r"(addr));
}
__device__ __forceinline__ void mma16816(float* c, const uint32_t* a, uint32_t b0, uint32_t b1) {
    asm volatile(
        "mma.sync.aligned.m16n8k16.row.col.f32.bf16.bf16.f32 "
        "{%0,%1,%2,%3}, {%4,%5,%6,%7}, {%8,%9}, {%0,%1,%2,%3};"
        : "+f"(c[0]), "+f"(c[1]), "+f"(c[2]), "+f"(c[3])
        : "r"(a[0]), "r"(a[1]), "r"(a[2]), "r"(a[3]), "r"(b0), "r"(b1));
}

// ---------------- K0: weight fp32 -> bf16 (+ zero counters) -------------------
__global__ __launch_bounds__(256) void k_convert(
    const float* __restrict__ Wg, const float* __restrict__ Wu,
    const float* __restrict__ Wd)
{
    if (blockIdx.x == 0 && blockIdx.y == 0 && threadIdx.x < NE) {
        g_cnt[threadIdx.x] = 0; g_top1[threadIdx.x] = 0; g_probsum[threadIdx.x] = 0.f;
    }
    const float* src; __nv_bfloat16* dst;
    if (blockIdx.y == 0)      { src = Wg; dst = g_Wgb; }
    else if (blockIdx.y == 1) { src = Wu; dst = g_Wub; }
    else                      { src = Wd; dst = g_Wdb; }
    size_t i = ((size_t)blockIdx.x * 256 + threadIdx.x) * 4;
    float4 v = *reinterpret_cast<const float4*>(src + i);
    __nv_bfloat162* d2 = reinterpret_cast<__nv_bfloat162*>(dst + i);
    d2[0] = __floats2bfloat162_rn(v.x, v.y);
    d2[1] = __floats2bfloat162_rn(v.z, v.w);
}

// ---------------- K1: RMSNorm + router + residual init ------------------------
__global__ __launch_bounds__(256) void k_norm_router(
    const float* __restrict__ x, const float* __restrict__ norm_w,
    const float* __restrict__ gate_w, float* __restrict__ out)
{
    int token = blockIdx.x;
    int tid   = threadIdx.x;
    __shared__ float s_xn[DM];
    __shared__ float s_red[8];
    __shared__ float s_logit[NE];
    __shared__ float s_prob[NE];

    const float2 v = reinterpret_cast<const float2*>(x + (size_t)token * DM)[tid];
    float ss = v.x * v.x + v.y * v.y;
    #pragma unroll
    for (int o = 16; o; o >>= 1) ss += __shfl_xor_sync(0xffffffffu, ss, o);
    if ((tid & 31) == 0) s_red[tid >> 5] = ss;
    __syncthreads();
    if (tid == 0) {
        float t = 0.f;
        #pragma unroll
        for (int i = 0; i < 8; i++) t += s_red[i];
        s_red[0] = rsqrtf(t / (float)DM + 1e-6f);
    }
    __syncthreads();
    float rstd = s_red[0];
    float2 nw = reinterpret_cast<const float2*>(norm_w)[tid];
    float a0 = v.x * rstd * nw.x;
    float a1 = v.y * rstd * nw.y;
    s_xn[2 * tid]     = a0;
    s_xn[2 * tid + 1] = a1;
    reinterpret_cast<float2*>(out + (size_t)token * DM)[tid] = v;   // residual
    reinterpret_cast<__nv_bfloat162*>(g_xn + (size_t)token * DM)[tid] =
        __floats2bfloat162_rn(a0, a1);
    __syncthreads();

    int w = tid >> 5, lane = tid & 31;
    {
        const float* gw = gate_w + w * DM;
        float acc = 0.f;
        #pragma unroll
        for (int j = lane; j < DM; j += 32) acc += s_xn[j] * gw[j];
        #pragma unroll
        for (int o = 16; o; o >>= 1) acc += __shfl_xor_sync(0xffffffffu, acc, o);
        if (lane == 0) s_logit[w] = acc;
    }
    __syncthreads();

    if (tid == 0) {
        float mx = -1e30f;
        #pragma unroll
        for (int e = 0; e < NE; e++) mx = fmaxf(mx, s_logit[e]);
        float p[NE]; float se = 0.f;
        #pragma unroll
        for (int e = 0; e < NE; e++) { p[e] = expf(s_logit[e] - mx); se += p[e]; }
        float inv = 1.f / se;
        int i1 = 0; float p1 = -1.f;
        #pragma unroll
        for (int e = 0; e < NE; e++) {
            p[e] *= inv; s_prob[e] = p[e];
            if (p[e] > p1) { p1 = p[e]; i1 = e; }
        }
        int i2 = 0; float p2 = -1.f;
        #pragma unroll
        for (int e = 0; e < NE; e++)
            if (e != i1 && p[e] > p2) { p2 = p[e]; i2 = e; }
        float sw = p1 + p2; if (sw < 1e-9f) sw = 1e-9f;
        g_topidx[token * 2]     = i1;
        g_topidx[token * 2 + 1] = i2;
        g_topw[token * 2]       = p1 / sw;
        g_topw[token * 2 + 1]   = p2 / sw;
        atomicAdd(&g_cnt[i1], 1);
        atomicAdd(&g_cnt[i2], 1);
        atomicAdd(&g_top1[i1], 1);
    }
    __syncthreads();
    if (tid < NE) atomicAdd(&g_probsum[tid], s_prob[tid]);
}

// ---------------- K2: offsets + tile map + warp-aggregated scatter -------------
__global__ __launch_bounds__(1024) void k_off_scatter() {
    __shared__ int s_cur[NE];
    int t = threadIdx.x;
    if (t < NE) s_cur[t] = 0;
    if (t == 0) {
        int a = 0, nt = 0;
        #pragma unroll
        for (int e = 0; e < NE; e++) {
            g_off[e] = a;
            int c = g_cnt[e];
            for (int m0 = 0; m0 < c; m0 += 128) {
                g_tile_e[nt] = e; g_tile_m0[nt] = m0; nt++;
            }
            a += c;
        }
        g_ntile = nt;
    }
    __syncthreads();
    int lane = t & 31;
    for (int tok = t; tok < NTOK; tok += 1024) {
        #pragma unroll
        for (int s = 0; s < TOPK; s++) {
            int e = g_topidx[2 * tok + s];
            unsigned m = __match_any_sync(0xffffffffu, e);
            int leader = __ffs(m) - 1;
            int rank = __popc(m & ((1u << lane) - 1u));
            int base = 0;
            if (lane == leader) base = atomicAdd(&s_cur[e], __popc(m));
            base = __shfl_sync(0xffffffffu, base, leader);
            int slot = g_off[e] + base + rank;
            g_perm[slot]  = tok;
            g_wcomb[slot] = g_topw[2 * tok + s];
        }
    }
}

// ---------------- K3: gate+up GEMM (mma.sync) + SwiGLU -------------------------
// Block tile M=128 tokens x N=128 (interleaved: even n = Wg row f0+n/2, odd = Wu).
// 8 warps: warp_m (0..1) x warp_n (0..3), warp tile 64x32. K=512, 8 chunks of 64.
__global__ __launch_bounds__(256, 2) void k_gateup()
{
    int ti = blockIdx.y;
    if (ti >= g_ntile) return;
    int e   = g_tile_e[ti];
    int m0  = g_tile_m0[ti];
    int cnt = g_cnt[e];
    int off = g_off[e];
    int f0  = blockIdx.x * 64;

    extern __shared__ char smem[];
    __shared__ int s_row[128];

    int t = threadIdx.x;
    if (t < 128) { int r = m0 + t; s_row[t] = (r < cnt) ? g_perm[off + r] : g_perm[off]; }
    __syncthreads();

    // cp.async descriptors: 4 A-chunks + 4 B-chunks per thread (16B each)
    uint32_t sbase = smem_u32(smem);
    const __nv_bfloat16* a_src[4]; uint32_t a_off[4];
    const __nv_bfloat16* b_src[4]; uint32_t b_off[4];
    #pragma unroll
    for (int j = 0; j < 4; j++) {
        int u = t * 4 + j;                 // 0..1023 = 128 rows x 8 chunks
        int row = u >> 3, q = u & 7;
        a_src[j] = g_xn + (size_t)s_row[row] * DM + q * 8;
        a_off[j] = row * 128 + ((q ^ (row & 7)) << 4);
        int f = f0 + (row >> 1);
        const __nv_bfloat16* wbase = (row & 1) ? g_Wub : g_Wgb;
        b_src[j] = wbase + ((size_t)e * FD + f) * DM + q * 8;
        b_off[j] = 16384 + row * 128 + ((q ^ (row & 7)) << 4);
    }

    auto issue = [&](int c) {
        uint32_t sb = sbase + (uint32_t)(c % NSTAGE) * STAGE_BYTES;
        int k0 = c * KC;
        #pragma unroll
        for (int j = 0; j < 4; j++) {
            cp16(sb + a_off[j], a_src[j] + k0);
            cp16(sb + b_off[j], b_src[j] + k0);
        }
        cp_commit();
    };

    int wid = t >> 5, lane = t & 31;
    int warp_m = wid >> 2, warp_n = wid & 3;
    int octet = lane >> 3, lr = lane & 7;

    // ldmatrix address precompute (row*128 and row&7 per fragment group)
    uint32_t aRow[4], aMsk[4], aCb = octet >> 1;
    #pragma unroll
    for (int i = 0; i < 4; i++) {
        int row = warp_m * 64 + i * 16 + (octet & 1) * 8 + lr;
        aRow[i] = row * 128; aMsk[i] = row & 7;
    }
    uint32_t bRow[2], bMsk[2], bCb = octet & 1;
    #pragma unroll
    for (int j2 = 0; j2 < 2; j2++) {
        int row = warp_n * 32 + j2 * 16 + (octet >> 1) * 8 + lr;
        bRow[j2] = 16384 + row * 128; bMsk[j2] = row & 7;
    }

    float acc[4][4][4];
    #pragma unroll
    for (int i = 0; i < 4; i++)
        #pragma unroll
        for (int j = 0; j < 4; j++)
            #pragma unroll
            for (int k = 0; k < 4; k++) acc[i][j][k] = 0.f;

    issue(0); issue(1);

    const int NCH = DM / KC;   // 8
    for (int c = 0; c < NCH; c++) {
        if (c == NCH - 1) asm volatile("cp.async.wait_group 0;\n" ::: "memory");
        else              asm volatile("cp.async.wait_group 1;\n" ::: "memory");
        __syncthreads();
        if (c + 2 < NCH) issue(c + 2);

        uint32_t sb = sbase + (uint32_t)(c % NSTAGE) * STAGE_BYTES;
        #pragma unroll
        for (int ks = 0; ks < 4; ks++) {
            uint32_t a[4][4], b[2][4];
            #pragma unroll
            for (int i = 0; i < 4; i++)
                ldmx4(a[i][0], a[i][1], a[i][2], a[i][3],
                      sb + aRow[i] + ((((ks << 1) | aCb) ^ aMsk[i]) << 4));
            #pragma unroll
            for (int j2 = 0; j2 < 2; j2++)
                ldmx4(b[j2][0], b[j2][1], b[j2][2], b[j2][3],
                      sb + bRow[j2] + ((((ks << 1) | bCb) ^ bMsk[j2]) << 4));
            #pragma unroll
            for (int i = 0; i < 4; i++)
                #pragma unroll
                for (int j2 = 0; j2 < 2; j2++) {
                    mma16816(acc[i][j2 * 2],     a[i], b[j2][0], b[j2][1]);
                    mma16816(acc[i][j2 * 2 + 1], a[i], b[j2][2], b[j2][3]);
                }
        }
    }
    __syncthreads();

    // SwiGLU epilogue: even col = G, odd col = U, same f → per-thread (c0,c1),(c2,c3)
    __nv_bfloat16* sH = (__nv_bfloat16*)smem;   // 128 x 72 (stride pad)
    int g = lane >> 2, tg = lane & 3;
    #pragma unroll
    for (int i = 0; i < 4; i++) {
        int r0 = warp_m * 64 + i * 16 + g;
        #pragma unroll
        for (int jn = 0; jn < 4; jn++) {
            int fcol = warp_n * 16 + jn * 4 + tg;
            float g0 = acc[i][jn][0], u0 = acc[i][jn][1];
            float g1 = acc[i][jn][2], u1 = acc[i][jn][3];
            sH[r0 * 72 + fcol]       = __float2bfloat16((g0 / (1.f + __expf(-g0))) * u0);
            sH[(r0 + 8) * 72 + fcol] = __float2bfloat16((g1 / (1.f + __expf(-g1))) * u1);
        }
    }
    __syncthreads();

    int lim = cnt - m0; if (lim > 128) lim = 128;
    for (int v = t; v < 128 * 8; v += 256) {   // 128 rows x 8 chunks of 8 bf16
        int row = v >> 3, q = v & 7;
        if (row < lim)
            *reinterpret_cast<uint4*>(g_H + (size_t)(off + m0 + row) * FD + f0 + q * 8) =
                *reinterpret_cast<uint4*>(sH + row * 72 + q * 8);
    }
}

// ---------------- K4: down GEMM (mma.sync) + weighted scatter-add --------------
// Block tile M=128 slots x N=128 d-cols. K=1024, 16 chunks of 64.
__global__ __launch_bounds__(256, 2) void k_down(float* __restrict__ out)
{
    int ti = blockIdx.y;
    if (ti >= g_ntile) return;
    int e   = g_tile_e[ti];
    int m0  = g_tile_m0[ti];
    int cnt = g_cnt[e];
    int off = g_off[e];
    int d0  = blockIdx.x * 128;

    extern __shared__ char smem[];
    __shared__ int   s_tok[128];
    __shared__ float s_w[128];

    int t = threadIdx.x;
    int lim = cnt - m0; if (lim > 128) lim = 128;
    if (t < 128) {
        if (t < lim) { s_tok[t] = g_perm[off + m0 + t]; s_w[t] = g_wcomb[off + m0 + t]; }
        else         { s_tok[t] = 0; s_w[t] = 0.f; }
    }
    __syncthreads();

    uint32_t sbase = smem_u32(smem);
    const __nv_bfloat16* a_src[4]; uint32_t a_off[4];
    const __nv_bfloat16* b_src[4]; uint32_t b_off[4];
    #pragma unroll
    for (int j = 0; j < 4; j++) {
        int u = t * 4 + j;
        int row = u >> 3, q = u & 7;
        int slot = off + m0 + row; if (slot >= NSLOT) slot = NSLOT - 1;
        a_src[j] = g_H + (size_t)slot * FD + q * 8;
        a_off[j] = row * 128 + ((q ^ (row & 7)) << 4);
        b_src[j] = g_Wdb + ((size_t)e * DM + d0 + row) * FD + q * 8;
        b_off[j] = 16384 + row * 128 + ((q ^ (row & 7)) << 4);
    }

    auto issue = [&](int c) {
        uint32_t sb = sbase + (uint32_t)(c % NSTAGE) * STAGE_BYTES;
        int k0 = c * KC;
        #pragma unroll
        for (int j = 0; j < 4; j++) {
            cp16(sb + a_off[j], a_src[j] + k0);
            cp16(sb + b_off[j], b_src[j] + k0);
        }
        cp_commit();
    };

    int wid = t >> 5, lane = t & 31;
    int warp_m = wid >> 2, warp_n = wid & 3;
    int octet = lane >> 3, lr = lane & 7;

    uint32_t aRow[4], aMsk[4], aCb = octet >> 1;
    #pragma unroll
    for (int i = 0; i < 4; i++) {
        int row = warp_m * 64 + i * 16 + (octet & 1) * 8 + lr;
        aRow[i] = row * 128; aMsk[i] = row & 7;
    }
    uint32_t bRow[2], bMsk[2], bCb = octet & 1;
    #pragma unroll
    for (int j2 = 0; j2 < 2; j2++) {
        int row = warp_n * 32 + j2 * 16 + (octet >> 1) * 8 + lr;
        bRow[j2] = 16384 + row * 128; bMsk[j2] = row & 7;
    }

    float acc[4][4][4];
    #pragma unroll
    for (int i = 0; i < 4; i++)
        #pragma unroll
        for (int j = 0; j < 4; j++)
            #pragma unroll
            for (int k = 0; k < 4; k++) acc[i][j][k] = 0.f;

    issue(0); issue(1);

    const int NCH = FD / KC;   // 16
    for (int c = 0; c < NCH; c++) {
        if (c == NCH - 1) asm volatile("cp.async.wait_group 0;\n" ::: "memory");
        else              asm volatile("cp.async.wait_group 1;\n" ::: "memory");
        __syncthreads();
        if (c + 2 < NCH) issue(c + 2);

        uint32_t sb = sbase + (uint32_t)(c % NSTAGE) * STAGE_BYTES;
        #pragma unroll
        for (int ks = 0; ks < 4; ks++) {
            uint32_t a[4][4], b[2][4];
            #pragma unroll
            for (int i = 0; i < 4; i++)
                ldmx4(a[i][0], a[i][1], a[i][2], a[i][3],
                      sb + aRow[i] + ((((ks << 1) | aCb) ^ aMsk[i]) << 4));
            #pragma unroll
            for (int j2 = 0; j2 < 2; j2++)
                ldmx4(b[j2][0], b[j2][1], b[j2][2], b[j2][3],
                      sb + bRow[j2] + ((((ks << 1) | bCb) ^ bMsk[j2]) << 4));
            #pragma unroll
            for (int i = 0; i < 4; i++)
                #pragma unroll
                for (int j2 = 0; j2 < 2; j2++) {
                    mma16816(acc[i][j2 * 2],     a[i], b[j2][0], b[j2][1]);
                    mma16816(acc[i][j2 * 2 + 1], a[i], b[j2][2], b[j2][3]);
                }
        }
    }
    __syncthreads();

    // stage f32 result, then weighted coalesced atomic scatter
    float* sO = (float*)smem;   // 128 x 132
    int g = lane >> 2, tg = lane & 3;
    #pragma unroll
    for (int i = 0; i < 4; i++) {
        int r0 = warp_m * 64 + i * 16 + g;
        #pragma unroll
        for (int jn = 0; jn < 4; jn++) {
            int n = warp_n * 32 + jn * 8 + tg * 2;
            *reinterpret_cast<float2*>(&sO[r0 * 132 + n])       = make_float2(acc[i][jn][0], acc[i][jn][1]);
            *reinterpret_cast<float2*>(&sO[(r0 + 8) * 132 + n]) = make_float2(acc[i][jn][2], acc[i][jn][3]);
        }
    }
    __syncthreads();

    for (int v = t; v < 128 * 32; v += 256) {   // 128 rows x 32 float4s
        int row = v >> 5, q = v & 31;
        if (row < lim) {
            float4 vv = *reinterpret_cast<float4*>(&sO[row * 132 + q * 4]);
            float w = s_w[row];
            float* o = out + (size_t)s_tok[row] * DM + d0 + q * 4;
            atomicAdd(o + 0, w * vv.x);
            atomicAdd(o + 1, w * vv.y);
            atomicAdd(o + 2, w * vv.z);
            atomicAdd(o + 3, w * vv.w);
        }
    }
}

// ---------------- K5: aux loss -------------------------------------------------
__global__ void k_aux(float* __restrict__ out, int out_size) {
    if (threadIdx.x == 0) {
        float s = 0.f;
        #pragma unroll
        for (int e = 0; e < NE; e++)
            s += ((float)g_top1[e] / (float)NTOK) * (g_probsum[e] / (float)NTOK);
        s *= (float)NE;
        if (out_size > NTOK * DM) out[NTOK * DM] = s;
    }
}

// ---------------- launch --------------------------------------------------------
extern "C" void kernel_launch(void* const* d_in, const int* in_sizes, int n_in,
                              void* d_out, int out_size)
{
    const float* x      = (const float*)d_in[0];
    const float* norm_w = (const float*)d_in[1];
    const float* gate_w = (const float*)d_in[2];
    const float* Wg     = (const float*)d_in[3];
    const float* Wu     = (const float*)d_in[4];
    const float* Wd     = (const float*)d_in[5];
    float* out = (float*)d_out;

    cudaFuncSetAttribute(k_gateup, cudaFuncAttributeMaxDynamicSharedMemorySize, SMEM_DYN);
    cudaFuncSetAttribute(k_down,   cudaFuncAttributeMaxDynamicSharedMemorySize, SMEM_DYN);

    k_convert<<<dim3(NE * FD * DM / 4 / 256, 3), 256>>>(Wg, Wu, Wd);
    k_norm_router<<<NTOK, 256>>>(x, norm_w, gate_w, out);
    k_off_scatter<<<1, 1024>>>();
    k_gateup<<<dim3(FD / 64, MAXTILE), 256, SMEM_DYN>>>();
    k_down<<<dim3(DM / 128, MAXTILE), 256, SMEM_DYN>>>(out);
    k_aux<<<1, 32>>>(out, out_size);
}